// round 15
// baseline (speedup 1.0000x reference)
#include <cuda_runtime.h>
#include <cuda_bf16.h>
#include <cstdint>

// DeepSpeed fixed sparse self-attention, B=2, H=16, S=2048, D=64, fp32.
// q-rows [64t,64t+64) attend window [64t,64t+48) + stripes [64m+48,64m+64), m=0..31.
// Math: mma.sync m16n8k16 bf16, 3-MMA split compensation (verified path).
// R15: split-K flash. 256-thr CTA = 2 warpgroups over the SAME 64 q-rows:
//   wg0: chunks 0..8 (window 32+16, stripes 0..13), wg1: chunks 9..17 (stripes 14..31).
// Each wg: own double-buffered stages + own named barrier -> wgs drift out of
// phase, overlapping one wg's softmax with the other's MMAs. Exact flash-merge
// at the end. 2 CTAs/SM x 8 warps = 16 warps/SM.

#define SEQ 2048
#define HD  64
#define NBH 32
#define NEGBIG (-1e30f)
#define SC2 0.18033688011112042f   // 0.125 * log2(e)

// smem (bytes): Q hi/lo, then 4 stage buffers (2 per wg).
// stage: KH +0, KL +4096, VH +8192, VL +12288 (32 rows x 128B each)
#define SM_QH 0
#define SM_QL 8192
#define SM_S0 16384
#define STG   16384
#define SM_TOTAL 81920

__device__ __align__(16) __nv_bfloat16 g_Kh[(size_t)NBH*SEQ*HD];
__device__ __align__(16) __nv_bfloat16 g_Kl[(size_t)NBH*SEQ*HD];
__device__ __align__(16) __nv_bfloat16 g_Vh[(size_t)NBH*SEQ*HD];
__device__ __align__(16) __nv_bfloat16 g_Vl[(size_t)NBH*SEQ*HD];

__device__ __forceinline__ void mma_bf16(float4& d,
                                         uint32_t a0, uint32_t a1, uint32_t a2, uint32_t a3,
                                         uint32_t b0, uint32_t b1)
{
    asm volatile(
        "mma.sync.aligned.m16n8k16.row.col.f32.bf16.bf16.f32 "
        "{%0,%1,%2,%3}, {%4,%5,%6,%7}, {%8,%9}, {%0,%1,%2,%3};\n"
        : "+f"(d.x), "+f"(d.y), "+f"(d.z), "+f"(d.w)
        : "r"(a0), "r"(a1), "r"(a2), "r"(a3), "r"(b0), "r"(b1));
}

__device__ __forceinline__ void ldsm_x4(uint32_t& r0, uint32_t& r1, uint32_t& r2, uint32_t& r3,
                                        uint32_t addr)
{
    asm volatile("ldmatrix.sync.aligned.m8n8.x4.shared.b16 {%0,%1,%2,%3}, [%4];"
                 : "=r"(r0), "=r"(r1), "=r"(r2), "=r"(r3) : "r"(addr));
}

__device__ __forceinline__ void ldsm_x4_t(uint32_t& r0, uint32_t& r1, uint32_t& r2, uint32_t& r3,
                                          uint32_t addr)
{
    asm volatile("ldmatrix.sync.aligned.m8n8.x4.trans.shared.b16 {%0,%1,%2,%3}, [%4];"
                 : "=r"(r0), "=r"(r1), "=r"(r2), "=r"(r3) : "r"(addr));
}

__device__ __forceinline__ void split2(float a, float b, uint32_t& h, uint32_t& l)
{
    __nv_bfloat162 hv = __floats2bfloat162_rn(a, b);
    h = *reinterpret_cast<uint32_t*>(&hv);
    float ra = a - __bfloat162float(hv.x);
    float rb = b - __bfloat162float(hv.y);
    __nv_bfloat162 lv = __floats2bfloat162_rn(ra, rb);
    l = *reinterpret_cast<uint32_t*>(&lv);
}

__device__ __forceinline__ void cp16(uint32_t dst, const void* src)
{
    asm volatile("cp.async.ca.shared.global [%0], [%1], 16;\n" :: "r"(dst), "l"(src));
}
__device__ __forceinline__ void cp_commit()
{
    asm volatile("cp.async.commit_group;\n" ::: "memory");
}
__device__ __forceinline__ void cp_wait_all()
{
    asm volatile("cp.async.wait_group 0;\n" ::: "memory");
}
__device__ __forceinline__ void wg_bar(int id)
{
    asm volatile("bar.sync %0, 128;" :: "r"(id) : "memory");
}

// ================= prepass: split K,V into bf16 hi/lo =================
__global__ void prepass_split(const float* __restrict__ K, const float* __restrict__ V, int n8)
{
    int i = blockIdx.x * blockDim.x + threadIdx.x;
    if (i >= n8) return;
    const float4* K4 = reinterpret_cast<const float4*>(K);
    const float4* V4 = reinterpret_cast<const float4*>(V);
    uint32_t h0,l0,h1,l1,h2,l2,h3,l3;

    float4 a = K4[2*i], b = K4[2*i+1];
    split2(a.x,a.y,h0,l0); split2(a.z,a.w,h1,l1);
    split2(b.x,b.y,h2,l2); split2(b.z,b.w,h3,l3);
    reinterpret_cast<uint4*>(g_Kh)[i] = make_uint4(h0,h1,h2,h3);
    reinterpret_cast<uint4*>(g_Kl)[i] = make_uint4(l0,l1,l2,l3);

    a = V4[2*i]; b = V4[2*i+1];
    split2(a.x,a.y,h0,l0); split2(a.z,a.w,h1,l1);
    split2(b.x,b.y,h2,l2); split2(b.z,b.w,h3,l3);
    reinterpret_cast<uint4*>(g_Vh)[i] = make_uint4(h0,h1,h2,h3);
    reinterpret_cast<uint4*>(g_Vl)[i] = make_uint4(l0,l1,l2,l3);
}

// ---- cp.async staging of chunk c: c0 = window 0..31, c1 = window 32..47,
//      c in [2,18) = stripes 2(c-2), 2(c-2)+1 ----
__device__ __forceinline__ void stage_cp(uint32_t kvb, int c, int t,
                                         const uint4* gkh, const uint4* gkl,
                                         const uint4* gvh, const uint4* gvl, int wtid)
{
    #pragma unroll
    for (int it = 0; it < 2; it++) {
        int idx = wtid + it * 128;             // 0..255
        int row = idx >> 3, ch = idx & 7;      // row 0..31
        if (c == 1 && row >= 16) break;        // half chunk
        int gk;
        if (c == 0)      gk = t * 64 + row;
        else if (c == 1) gk = t * 64 + 32 + row;
        else {
            int stripe = 2 * (c - 2) + (row >> 4);   // 0..31
            gk = stripe * 64 + 48 + (row & 15);
        }
        size_t go = (size_t)gk * 8 + ch;
        uint32_t sw = (uint32_t)(row * 128 + ((ch ^ (row & 7)) << 4));
        cp16(kvb + sw,          gkh + go);
        cp16(kvb + 4096 + sw,   gkl + go);
        cp16(kvb + 8192 + sw,   gvh + go);
        cp16(kvb + 12288 + sw,  gvl + go);
    }
}

// ================= per-chunk compute (verified fragment maps) =================
// NTP: x4 K-fragment pairs (1 => 16 keys, 2 => 32 keys). w4 = warp-in-wg.
template<int NTP, bool FIRST>
__device__ __forceinline__ void compute_chunk(
    uint32_t smb, uint32_t kvb, float4 (&o)[8],
    float& m0, float& m1, float& l0, float& l1, int lane, int w4)
{
    const int arow  = (w4 << 4) + (((lane >> 3) & 1) << 3) + (lane & 7);
    const int krow0 = ((lane >> 4) << 3) + (lane & 7);
    const int kchp  = (lane >> 3) & 1;
    const int vrow0 = (((lane >> 3) & 1) << 3) + (lane & 7);
    const int vchp  = lane >> 4;

    float4 s[2 * NTP];
    #pragma unroll
    for (int i = 0; i < 2 * NTP; i++) s[i] = make_float4(0.f, 0.f, 0.f, 0.f);

    // ---- QK ----
    #pragma unroll
    for (int kb = 0; kb < 4; kb++) {
        const int qch = kb * 2 + (lane >> 4);
        const uint32_t qa = smb + SM_QH + arow * 128 + ((qch ^ (arow & 7)) << 4);
        uint32_t ah0, ah1, ah2, ah3, al0, al1, al2, al3;
        ldsm_x4(ah0, ah1, ah2, ah3, qa);
        ldsm_x4(al0, al1, al2, al3, qa + (SM_QL - SM_QH));
        #pragma unroll
        for (int ntp = 0; ntp < NTP; ntp++) {
            const int krow = ntp * 16 + krow0;
            const int kch  = kb * 2 + kchp;
            const uint32_t ka = kvb + krow * 128 + ((kch ^ (krow & 7)) << 4);
            uint32_t kl0, kl1, kl2, kl3, kh0, kh1, kh2, kh3;
            ldsm_x4(kl0, kl1, kl2, kl3, ka + 4096);   // K lo
            ldsm_x4(kh0, kh1, kh2, kh3, ka);          // K hi
            mma_bf16(s[2 * ntp],     ah0, ah1, ah2, ah3, kl0, kl1);   // Qh*Kl
            mma_bf16(s[2 * ntp],     al0, al1, al2, al3, kh0, kh1);   // Ql*Kh
            mma_bf16(s[2 * ntp],     ah0, ah1, ah2, ah3, kh0, kh1);   // Qh*Kh
            mma_bf16(s[2 * ntp + 1], ah0, ah1, ah2, ah3, kl2, kl3);
            mma_bf16(s[2 * ntp + 1], al0, al1, al2, al3, kh2, kh3);
            mma_bf16(s[2 * ntp + 1], ah0, ah1, ah2, ah3, kh2, kh3);
        }
    }

    // ---- streaming softmax (base-2) ----
    float rm0 = NEGBIG, rm1 = NEGBIG;
    #pragma unroll
    for (int nt = 0; nt < 2 * NTP; nt++) {
        s[nt].x *= SC2; s[nt].y *= SC2; s[nt].z *= SC2; s[nt].w *= SC2;
        rm0 = fmaxf(rm0, fmaxf(s[nt].x, s[nt].y));
        rm1 = fmaxf(rm1, fmaxf(s[nt].z, s[nt].w));
    }
    rm0 = fmaxf(rm0, __shfl_xor_sync(0xffffffffu, rm0, 1));
    rm0 = fmaxf(rm0, __shfl_xor_sync(0xffffffffu, rm0, 2));
    rm1 = fmaxf(rm1, __shfl_xor_sync(0xffffffffu, rm1, 1));
    rm1 = fmaxf(rm1, __shfl_xor_sync(0xffffffffu, rm1, 2));

    float mn0, mn1;
    if (FIRST) { mn0 = rm0; mn1 = rm1; }
    else       { mn0 = fmaxf(m0, rm0); mn1 = fmaxf(m1, rm1); }

    float rs0 = 0.f, rs1 = 0.f;
    #pragma unroll
    for (int nt = 0; nt < 2 * NTP; nt++) {
        s[nt].x = exp2f(s[nt].x - mn0);
        s[nt].y = exp2f(s[nt].y - mn0);
        s[nt].z = exp2f(s[nt].z - mn1);
        s[nt].w = exp2f(s[nt].w - mn1);
        rs0 += s[nt].x + s[nt].y;
        rs1 += s[nt].z + s[nt].w;
    }
    rs0 += __shfl_xor_sync(0xffffffffu, rs0, 1);
    rs0 += __shfl_xor_sync(0xffffffffu, rs0, 2);
    rs1 += __shfl_xor_sync(0xffffffffu, rs1, 1);
    rs1 += __shfl_xor_sync(0xffffffffu, rs1, 2);

    if (FIRST) {
        l0 = rs0; l1 = rs1; m0 = mn0; m1 = mn1;
    } else {
        const float alp0 = exp2f(m0 - mn0), alp1 = exp2f(m1 - mn1);
        m0 = mn0; m1 = mn1;
        l0 = l0 * alp0 + rs0;
        l1 = l1 * alp1 + rs1;
        #pragma unroll
        for (int dt = 0; dt < 8; dt++) {
            o[dt].x *= alp0; o[dt].y *= alp0;
            o[dt].z *= alp1; o[dt].w *= alp1;
        }
    }

    // ---- PV ----
    #pragma unroll
    for (int kb = 0; kb < NTP; kb++) {
        uint32_t ph0, pl0, ph1, pl1, ph2, pl2, ph3, pl3;
        split2(s[2 * kb].x,     s[2 * kb].y,     ph0, pl0);
        split2(s[2 * kb].z,     s[2 * kb].w,     ph1, pl1);
        split2(s[2 * kb + 1].x, s[2 * kb + 1].y, ph2, pl2);
        split2(s[2 * kb + 1].z, s[2 * kb + 1].w, ph3, pl3);
        const int vrow = kb * 16 + vrow0;
        #pragma unroll
        for (int dtp = 0; dtp < 4; dtp++) {
            const int vch = dtp * 2 + vchp;
            const uint32_t va = kvb + 8192 + vrow * 128 + ((vch ^ (vrow & 7)) << 4);
            uint32_t vh0, vh1, vh2, vh3, vl0, vl1, vl2, vl3;
            ldsm_x4_t(vh0, vh1, vh2, vh3, va);          // V hi
            ldsm_x4_t(vl0, vl1, vl2, vl3, va + 4096);   // V lo
            mma_bf16(o[2 * dtp],     ph0, ph1, ph2, ph3, vl0, vl1);   // Ph*Vl
            mma_bf16(o[2 * dtp],     pl0, pl1, pl2, pl3, vh0, vh1);   // Pl*Vh
            mma_bf16(o[2 * dtp],     ph0, ph1, ph2, ph3, vh0, vh1);   // Ph*Vh
            mma_bf16(o[2 * dtp + 1], ph0, ph1, ph2, ph3, vl2, vl3);
            mma_bf16(o[2 * dtp + 1], pl0, pl1, pl2, pl3, vh2, vh3);
            mma_bf16(o[2 * dtp + 1], ph0, ph1, ph2, ph3, vh2, vh3);
        }
    }
}

// ================= main kernel =================
__global__ void __launch_bounds__(256, 2)
sparse_attn_bf16(const float* __restrict__ Q, float* __restrict__ Out)
{
    extern __shared__ __align__(16) char sm[];
    const uint32_t smb = (uint32_t)__cvta_generic_to_shared(sm);

    const int tid  = threadIdx.x;
    const int warp = tid >> 5;
    const int lane = tid & 31;
    const int g    = lane >> 2;
    const int q4   = lane & 3;
    const int wg   = warp >> 2;           // warpgroup 0/1
    const int w4   = warp & 3;            // warp in wg
    const int wtid = tid & 127;
    const int t    = blockIdx.x;          // q tile 0..31
    const int bh   = blockIdx.y;

    const size_t base = (size_t)bh * SEQ * HD;
    const float* Qg = Q + base + (size_t)t * 64 * HD;
    float*       Og = Out + base + (size_t)t * 64 * HD;
    const uint4* gkh = reinterpret_cast<const uint4*>(g_Kh + base);
    const uint4* gkl = reinterpret_cast<const uint4*>(g_Kl + base);
    const uint4* gvh = reinterpret_cast<const uint4*>(g_Vh + base);
    const uint4* gvl = reinterpret_cast<const uint4*>(g_Vl + base);

    const uint32_t sbase = smb + SM_S0 + (uint32_t)wg * (2 * STG);
    const int cbase = wg * 9;             // wg0: chunks 0..8, wg1: 9..17

    // issue this wg's first chunk
    stage_cp(sbase, cbase, t, gkh, gkl, gvh, gvl, wtid);
    cp_commit();

    // ---- stage Q hi/lo (all 256 threads) while chunk flies ----
    #pragma unroll
    for (int it = 0; it < 2; it++) {
        int idx = tid + it * 256;             // 0..511
        int r = idx >> 3, ch = idx & 7;
        const float4* src = reinterpret_cast<const float4*>(Qg + r * HD + ch * 8);
        float4 a = src[0], b = src[1];
        uint32_t h0,l0,h1,l1,h2,l2,h3,l3;
        split2(a.x,a.y,h0,l0); split2(a.z,a.w,h1,l1);
        split2(b.x,b.y,h2,l2); split2(b.z,b.w,h3,l3);
        uint32_t sw = (uint32_t)(r * 128 + ((ch ^ (r & 7)) << 4));
        *reinterpret_cast<uint4*>(sm + SM_QH + sw) = make_uint4(h0,h1,h2,h3);
        *reinterpret_cast<uint4*>(sm + SM_QL + sw) = make_uint4(l0,l1,l2,l3);
    }
    __syncthreads();   // Q visible to both wgs; wg streams diverge after this

    float4 o[8];
    #pragma unroll
    for (int i = 0; i < 8; i++) o[i] = make_float4(0.f, 0.f, 0.f, 0.f);
    float m0 = 0.f, m1 = 0.f, l0 = 0.f, l1 = 0.f;
    const int r0 = w4 * 16 + g;

    // ---- 9 chunks per wg, own named barrier, cp.async one chunk ahead ----
    #pragma unroll 1
    for (int i = 0; i < 9; i++) {
        cp_wait_all();
        wg_bar(1 + wg);      // chunk i visible in this wg; compute(i-1) done
        if (i < 8)
            stage_cp(sbase + ((i + 1) & 1) * STG, cbase + i + 1, t,
                     gkh, gkl, gvh, gvl, wtid);
        cp_commit();
        const uint32_t kvb = sbase + (i & 1) * STG;
        if (i == 0)
            compute_chunk<2, true >(smb, kvb, o, m0, m1, l0, l1, lane, w4);
        else if (wg == 0 && i == 1)
            compute_chunk<1, false>(smb, kvb, o, m0, m1, l0, l1, lane, w4);
        else
            compute_chunk<2, false>(smb, kvb, o, m0, m1, l0, l1, lane, w4);
    }

    // ---- merge the two wg states (exact flash-combine) ----
    __syncthreads();     // both wgs done; stage buffers reusable
    float4* mo4 = reinterpret_cast<float4*>(sm + SM_S0);          // [8][128]
    float4* mst = reinterpret_cast<float4*>(sm + SM_S0 + 16384);  // [128]
    if (wg == 1) {
        #pragma unroll
        for (int j = 0; j < 8; j++) mo4[j * 128 + wtid] = o[j];
        mst[wtid] = make_float4(m0, m1, l0, l1);
    }
    __syncthreads();
    if (wg == 0) {
        float4 st = mst[wtid];
        const float M0 = fmaxf(m0, st.x), M1 = fmaxf(m1, st.y);
        const float aA0 = exp2f(m0 - M0), aB0 = exp2f(st.x - M0);
        const float aA1 = exp2f(m1 - M1), aB1 = exp2f(st.y - M1);
        const float i0 = 1.f / (l0 * aA0 + st.z * aB0);
        const float i1 = 1.f / (l1 * aA1 + st.w * aB1);
        #pragma unroll
        for (int dt = 0; dt < 8; dt++) {
            float4 ob = mo4[dt * 128 + wtid];
            *reinterpret_cast<float2*>(Og + r0 * HD + dt * 8 + 2 * q4) =
                make_float2((o[dt].x * aA0 + ob.x * aB0) * i0,
                            (o[dt].y * aA0 + ob.y * aB0) * i0);
            *reinterpret_cast<float2*>(Og + (r0 + 8) * HD + dt * 8 + 2 * q4) =
                make_float2((o[dt].z * aA1 + ob.z * aB1) * i1,
                            (o[dt].w * aA1 + ob.w * aB1) * i1);
        }
    }
}

extern "C" void kernel_launch(void* const* d_in, const int* in_sizes, int n_in,
                              void* d_out, int out_size)
{
    const float* Q = (const float*)d_in[0];
    const float* K = (const float*)d_in[1];
    const float* V = (const float*)d_in[2];
    float* O = (float*)d_out;

    const int nbh = in_sizes[0] / (SEQ * HD);      // 32
    const int n8  = nbh * SEQ * HD / 8;
    prepass_split<<<(n8 + 255) / 256, 256>>>(K, V, n8);

    cudaFuncSetAttribute(sparse_attn_bf16,
                         cudaFuncAttributeMaxDynamicSharedMemorySize, SM_TOTAL);
    dim3 grid(SEQ / 64, nbh);
    sparse_attn_bf16<<<grid, 256, SM_TOTAL>>>(Q, O);
}

// round 16
// speedup vs baseline: 1.0417x; 1.0417x over previous
#include <cuda_runtime.h>
#include <cuda_bf16.h>
#include <cstdint>

// DeepSpeed fixed sparse self-attention, B=2, H=16, S=2048, D=64, fp32.
// q-rows [64t,64t+64) attend window [64t,64t+48) + stripes [64m+48,64m+64), m=0..31.
// Math: mma.sync m16n8k16 bf16, 3-MMA split compensation (R14-verified).
// R16: NO bar.sync in the hot loop. Per-buffer full/empty mbarriers; warps
// free-run through 18 chunks (skew < 2 chunks via 2-buffer ring). Stager duty
// rotates (warp j&3 stages chunk j via 32-lane cp.async +
// cp.async.mbarrier.arrive.noinc) creating built-in warp skew -> one warp's
// MMA burst overlaps another's softmax. 4 CTAs/SM x 128 thr.

#define SEQ 2048
#define HD  64
#define NBH 32
#define NEGBIG (-1e30f)
#define SC2 0.18033688011112042f   // 0.125 * log2(e)

// smem layout (bytes)
#define SM_MBAR 0        // full0 @0, full1 @8, empty0 @16, empty1 @24
#define SM_QH   128
#define SM_QL   (128 + 8192)
#define SM_S0   (128 + 16384)
#define STG     16384    // stage: KH +0, KL +4096, VH +8192, VL +12288
#define SM_TOTAL (128 + 16384 + 2 * 16384)   // 49280

__device__ __align__(16) __nv_bfloat16 g_Kh[(size_t)NBH*SEQ*HD];
__device__ __align__(16) __nv_bfloat16 g_Kl[(size_t)NBH*SEQ*HD];
__device__ __align__(16) __nv_bfloat16 g_Vh[(size_t)NBH*SEQ*HD];
__device__ __align__(16) __nv_bfloat16 g_Vl[(size_t)NBH*SEQ*HD];

__device__ __forceinline__ void mma_bf16(float4& d,
                                         uint32_t a0, uint32_t a1, uint32_t a2, uint32_t a3,
                                         uint32_t b0, uint32_t b1)
{
    asm volatile(
        "mma.sync.aligned.m16n8k16.row.col.f32.bf16.bf16.f32 "
        "{%0,%1,%2,%3}, {%4,%5,%6,%7}, {%8,%9}, {%0,%1,%2,%3};\n"
        : "+f"(d.x), "+f"(d.y), "+f"(d.z), "+f"(d.w)
        : "r"(a0), "r"(a1), "r"(a2), "r"(a3), "r"(b0), "r"(b1));
}

__device__ __forceinline__ void ldsm_x4(uint32_t& r0, uint32_t& r1, uint32_t& r2, uint32_t& r3,
                                        uint32_t addr)
{
    asm volatile("ldmatrix.sync.aligned.m8n8.x4.shared.b16 {%0,%1,%2,%3}, [%4];"
                 : "=r"(r0), "=r"(r1), "=r"(r2), "=r"(r3) : "r"(addr));
}

__device__ __forceinline__ void ldsm_x4_t(uint32_t& r0, uint32_t& r1, uint32_t& r2, uint32_t& r3,
                                          uint32_t addr)
{
    asm volatile("ldmatrix.sync.aligned.m8n8.x4.trans.shared.b16 {%0,%1,%2,%3}, [%4];"
                 : "=r"(r0), "=r"(r1), "=r"(r2), "=r"(r3) : "r"(addr));
}

__device__ __forceinline__ void split2(float a, float b, uint32_t& h, uint32_t& l)
{
    __nv_bfloat162 hv = __floats2bfloat162_rn(a, b);
    h = *reinterpret_cast<uint32_t*>(&hv);
    float ra = a - __bfloat162float(hv.x);
    float rb = b - __bfloat162float(hv.y);
    __nv_bfloat162 lv = __floats2bfloat162_rn(ra, rb);
    l = *reinterpret_cast<uint32_t*>(&lv);
}

__device__ __forceinline__ void cp16(uint32_t dst, const void* src)
{
    asm volatile("cp.async.ca.shared.global [%0], [%1], 16;\n" :: "r"(dst), "l"(src));
}

// mbarrier primitives (sm_80+; compiled fine on sm_100 in R10)
__device__ __forceinline__ void mbar_init(uint32_t addr, uint32_t count)
{
    asm volatile("mbarrier.init.shared.b64 [%0], %1;" :: "r"(addr), "r"(count) : "memory");
}
__device__ __forceinline__ void mbar_arrive(uint32_t addr)
{
    asm volatile("mbarrier.arrive.shared.b64 _, [%0];" :: "r"(addr) : "memory");
}
__device__ __forceinline__ void cp_mbar_arrive_noinc(uint32_t addr)
{
    asm volatile("cp.async.mbarrier.arrive.noinc.shared::cta.b64 [%0];"
                 :: "r"(addr) : "memory");
}
__device__ __forceinline__ void mbar_wait(uint32_t mbar, uint32_t parity)
{
    uint32_t done;
    asm volatile(
        "{\n\t.reg .pred p;\n\t"
        "mbarrier.try_wait.parity.acquire.cta.shared::cta.b64 p, [%1], %2;\n\t"
        "selp.b32 %0, 1, 0, p;\n\t}"
        : "=r"(done) : "r"(mbar), "r"(parity) : "memory");
    if (!done) {
        asm volatile(
            "{\n\t.reg .pred P1;\n\t"
            "WL_%=:\n\t"
            "mbarrier.try_wait.parity.acquire.cta.shared::cta.b64 P1, [%0], %1, 0x989680;\n\t"
            "@P1 bra.uni WD_%=;\n\t"
            "bra.uni WL_%=;\n\t"
            "WD_%=:\n\t}"
            :: "r"(mbar), "r"(parity) : "memory");
    }
}

// ================= prepass: split K,V into bf16 hi/lo =================
__global__ void prepass_split(const float* __restrict__ K, const float* __restrict__ V, int n8)
{
    int i = blockIdx.x * blockDim.x + threadIdx.x;
    if (i >= n8) return;
    const float4* K4 = reinterpret_cast<const float4*>(K);
    const float4* V4 = reinterpret_cast<const float4*>(V);
    uint32_t h0,l0,h1,l1,h2,l2,h3,l3;

    float4 a = K4[2*i], b = K4[2*i+1];
    split2(a.x,a.y,h0,l0); split2(a.z,a.w,h1,l1);
    split2(b.x,b.y,h2,l2); split2(b.z,b.w,h3,l3);
    reinterpret_cast<uint4*>(g_Kh)[i] = make_uint4(h0,h1,h2,h3);
    reinterpret_cast<uint4*>(g_Kl)[i] = make_uint4(l0,l1,l2,l3);

    a = V4[2*i]; b = V4[2*i+1];
    split2(a.x,a.y,h0,l0); split2(a.z,a.w,h1,l1);
    split2(b.x,b.y,h2,l2); split2(b.z,b.w,h3,l3);
    reinterpret_cast<uint4*>(g_Vh)[i] = make_uint4(h0,h1,h2,h3);
    reinterpret_cast<uint4*>(g_Vl)[i] = make_uint4(l0,l1,l2,l3);
}

// ---- single-warp cp.async staging of chunk c into buffer kvb ----
// c0 = window keys 0..31, c1 = window 32..47 (16 keys),
// c in [2,18) = stripes 2(c-2), 2(c-2)+1 (keys 64m+48..64m+63 each).
__device__ __forceinline__ void stage_warp(uint32_t kvb, int c, int t,
                                           const uint4* gkh, const uint4* gkl,
                                           const uint4* gvh, const uint4* gvl, int lane)
{
    #pragma unroll
    for (int it = 0; it < 8; it++) {
        int idx = lane + it * 32;              // 0..255
        int row = idx >> 3, ch = idx & 7;      // row 0..31
        if (c == 1 && row >= 16) break;        // half chunk
        int gk;
        if (c == 0)      gk = t * 64 + row;
        else if (c == 1) gk = t * 64 + 32 + row;
        else {
            int stripe = 2 * (c - 2) + (row >> 4);   // 0..31
            gk = stripe * 64 + 48 + (row & 15);
        }
        size_t go = (size_t)gk * 8 + ch;
        uint32_t sw = (uint32_t)(row * 128 + ((ch ^ (row & 7)) << 4));
        cp16(kvb + sw,          gkh + go);
        cp16(kvb + 4096 + sw,   gkl + go);
        cp16(kvb + 8192 + sw,   gvh + go);
        cp16(kvb + 12288 + sw,  gvl + go);
    }
}

// ================= per-chunk compute (R14-verified fragment maps) =================
template<int NTP, bool FIRST>
__device__ __forceinline__ void compute_chunk(
    uint32_t smb, uint32_t kvb, float4 (&o)[8],
    float& m0, float& m1, float& l0, float& l1, int lane, int warp)
{
    const int arow  = (warp << 4) + (((lane >> 3) & 1) << 3) + (lane & 7);
    const int krow0 = ((lane >> 4) << 3) + (lane & 7);
    const int kchp  = (lane >> 3) & 1;
    const int vrow0 = (((lane >> 3) & 1) << 3) + (lane & 7);
    const int vchp  = lane >> 4;

    float4 s[2 * NTP];
    #pragma unroll
    for (int i = 0; i < 2 * NTP; i++) s[i] = make_float4(0.f, 0.f, 0.f, 0.f);

    // ---- QK ----
    #pragma unroll
    for (int kb = 0; kb < 4; kb++) {
        const int qch = kb * 2 + (lane >> 4);
        const uint32_t qa = smb + SM_QH + arow * 128 + ((qch ^ (arow & 7)) << 4);
        uint32_t ah0, ah1, ah2, ah3, al0, al1, al2, al3;
        ldsm_x4(ah0, ah1, ah2, ah3, qa);
        ldsm_x4(al0, al1, al2, al3, qa + (SM_QL - SM_QH));
        #pragma unroll
        for (int ntp = 0; ntp < NTP; ntp++) {
            const int krow = ntp * 16 + krow0;
            const int kch  = kb * 2 + kchp;
            const uint32_t ka = kvb + krow * 128 + ((kch ^ (krow & 7)) << 4);
            uint32_t kl0, kl1, kl2, kl3, kh0, kh1, kh2, kh3;
            ldsm_x4(kl0, kl1, kl2, kl3, ka + 4096);   // K lo
            ldsm_x4(kh0, kh1, kh2, kh3, ka);          // K hi
            mma_bf16(s[2 * ntp],     ah0, ah1, ah2, ah3, kl0, kl1);   // Qh*Kl
            mma_bf16(s[2 * ntp],     al0, al1, al2, al3, kh0, kh1);   // Ql*Kh
            mma_bf16(s[2 * ntp],     ah0, ah1, ah2, ah3, kh0, kh1);   // Qh*Kh
            mma_bf16(s[2 * ntp + 1], ah0, ah1, ah2, ah3, kl2, kl3);
            mma_bf16(s[2 * ntp + 1], al0, al1, al2, al3, kh2, kh3);
            mma_bf16(s[2 * ntp + 1], ah0, ah1, ah2, ah3, kh2, kh3);
        }
    }

    // ---- streaming softmax (base-2) ----
    float rm0 = NEGBIG, rm1 = NEGBIG;
    #pragma unroll
    for (int nt = 0; nt < 2 * NTP; nt++) {
        s[nt].x *= SC2; s[nt].y *= SC2; s[nt].z *= SC2; s[nt].w *= SC2;
        rm0 = fmaxf(rm0, fmaxf(s[nt].x, s[nt].y));
        rm1 = fmaxf(rm1, fmaxf(s[nt].z, s[nt].w));
    }
    rm0 = fmaxf(rm0, __shfl_xor_sync(0xffffffffu, rm0, 1));
    rm0 = fmaxf(rm0, __shfl_xor_sync(0xffffffffu, rm0, 2));
    rm1 = fmaxf(rm1, __shfl_xor_sync(0xffffffffu, rm1, 1));
    rm1 = fmaxf(rm1, __shfl_xor_sync(0xffffffffu, rm1, 2));

    float mn0, mn1;
    if (FIRST) { mn0 = rm0; mn1 = rm1; }
    else       { mn0 = fmaxf(m0, rm0); mn1 = fmaxf(m1, rm1); }

    float rs0 = 0.f, rs1 = 0.f;
    #pragma unroll
    for (int nt = 0; nt < 2 * NTP; nt++) {
        s[nt].x = exp2f(s[nt].x - mn0);
        s[nt].y = exp2f(s[nt].y - mn0);
        s[nt].z = exp2f(s[nt].z - mn1);
        s[nt].w = exp2f(s[nt].w - mn1);
        rs0 += s[nt].x + s[nt].y;
        rs1 += s[nt].z + s[nt].w;
    }
    rs0 += __shfl_xor_sync(0xffffffffu, rs0, 1);
    rs0 += __shfl_xor_sync(0xffffffffu, rs0, 2);
    rs1 += __shfl_xor_sync(0xffffffffu, rs1, 1);
    rs1 += __shfl_xor_sync(0xffffffffu, rs1, 2);

    if (FIRST) {
        l0 = rs0; l1 = rs1; m0 = mn0; m1 = mn1;
    } else {
        const float alp0 = exp2f(m0 - mn0), alp1 = exp2f(m1 - mn1);
        m0 = mn0; m1 = mn1;
        l0 = l0 * alp0 + rs0;
        l1 = l1 * alp1 + rs1;
        #pragma unroll
        for (int dt = 0; dt < 8; dt++) {
            o[dt].x *= alp0; o[dt].y *= alp0;
            o[dt].z *= alp1; o[dt].w *= alp1;
        }
    }

    // ---- PV ----
    #pragma unroll
    for (int kb = 0; kb < NTP; kb++) {
        uint32_t ph0, pl0, ph1, pl1, ph2, pl2, ph3, pl3;
        split2(s[2 * kb].x,     s[2 * kb].y,     ph0, pl0);
        split2(s[2 * kb].z,     s[2 * kb].w,     ph1, pl1);
        split2(s[2 * kb + 1].x, s[2 * kb + 1].y, ph2, pl2);
        split2(s[2 * kb + 1].z, s[2 * kb + 1].w, ph3, pl3);
        const int vrow = kb * 16 + vrow0;
        #pragma unroll
        for (int dtp = 0; dtp < 4; dtp++) {
            const int vch = dtp * 2 + vchp;
            const uint32_t va = kvb + 8192 + vrow * 128 + ((vch ^ (vrow & 7)) << 4);
            uint32_t vh0, vh1, vh2, vh3, vl0, vl1, vl2, vl3;
            ldsm_x4_t(vh0, vh1, vh2, vh3, va);          // V hi
            ldsm_x4_t(vl0, vl1, vl2, vl3, va + 4096);   // V lo
            mma_bf16(o[2 * dtp],     ph0, ph1, ph2, ph3, vl0, vl1);   // Ph*Vl
            mma_bf16(o[2 * dtp],     pl0, pl1, pl2, pl3, vh0, vh1);   // Pl*Vh
            mma_bf16(o[2 * dtp],     ph0, ph1, ph2, ph3, vh0, vh1);   // Ph*Vh
            mma_bf16(o[2 * dtp + 1], ph0, ph1, ph2, ph3, vl2, vl3);
            mma_bf16(o[2 * dtp + 1], pl0, pl1, pl2, pl3, vh2, vh3);
            mma_bf16(o[2 * dtp + 1], ph0, ph1, ph2, ph3, vh2, vh3);
        }
    }
}

// ================= main kernel =================
__global__ void __launch_bounds__(128, 4)
sparse_attn_bf16(const float* __restrict__ Q, float* __restrict__ Out)
{
    extern __shared__ __align__(16) char sm[];
    const uint32_t smb = (uint32_t)__cvta_generic_to_shared(sm);

    const int tid  = threadIdx.x;
    const int warp = tid >> 5;
    const int lane = tid & 31;
    const int g    = lane >> 2;
    const int q4   = lane & 3;
    const int t    = blockIdx.x;          // q tile 0..31
    const int bh   = blockIdx.y;

    const size_t base = (size_t)bh * SEQ * HD;
    const float* Qg = Q + base + (size_t)t * 64 * HD;
    float*       Og = Out + base + (size_t)t * 64 * HD;
    const uint4* gkh = reinterpret_cast<const uint4*>(g_Kh + base);
    const uint4* gkl = reinterpret_cast<const uint4*>(g_Kl + base);
    const uint4* gvh = reinterpret_cast<const uint4*>(g_Vh + base);
    const uint4* gvl = reinterpret_cast<const uint4*>(g_Vl + base);

    // mbarrier addresses: full[b] @ smb + b*8, empty[b] @ smb + 16 + b*8
    if (tid == 0) {
        mbar_init(smb + 0, 32);   // full0  (32 lane cp-arrives)
        mbar_init(smb + 8, 32);   // full1
        mbar_init(smb + 16, 4);   // empty0 (4 warp arrives)
        mbar_init(smb + 24, 4);   // empty1
    }
    __syncthreads();   // init visible before any arrive

    // prologue staging: warp0 -> chunk0/buf0, warp1 -> chunk1/buf1
    if (warp == 0) {
        stage_warp(smb + SM_S0, 0, t, gkh, gkl, gvh, gvl, lane);
        cp_mbar_arrive_noinc(smb + 0);
    } else if (warp == 1) {
        stage_warp(smb + SM_S0 + STG, 1, t, gkh, gkl, gvh, gvl, lane);
        cp_mbar_arrive_noinc(smb + 8);
    }

    // ---- stage Q hi/lo (all 128 threads, plain stores) ----
    #pragma unroll
    for (int it = 0; it < 4; it++) {
        int idx = tid + it * 128;             // 0..511
        int r = idx >> 3, ch = idx & 7;
        const float4* src = reinterpret_cast<const float4*>(Qg + r * HD + ch * 8);
        float4 a = src[0], b = src[1];
        uint32_t h0,l0,h1,l1,h2,l2,h3,l3;
        split2(a.x,a.y,h0,l0); split2(a.z,a.w,h1,l1);
        split2(b.x,b.y,h2,l2); split2(b.z,b.w,h3,l3);
        uint32_t sw = (uint32_t)(r * 128 + ((ch ^ (r & 7)) << 4));
        *reinterpret_cast<uint4*>(sm + SM_QH + sw) = make_uint4(h0,h1,h2,h3);
        *reinterpret_cast<uint4*>(sm + SM_QL + sw) = make_uint4(l0,l1,l2,l3);
    }
    __syncthreads();   // Q visible; LAST CTA-wide barrier — loop is barrier-free

    float4 o[8];
    #pragma unroll
    for (int i = 0; i < 8; i++) o[i] = make_float4(0.f, 0.f, 0.f, 0.f);
    float m0 = 0.f, m1 = 0.f, l0 = 0.f, l1 = 0.f;
    const int r0 = warp * 16 + g;

    // ---- 18 chunks, free-running warps, rotating stager ----
    #pragma unroll 1
    for (int i = 0; i < 18; i++) {
        const int b = i & 1;
        const int j = i + 1;                   // chunk to prefetch
        if (j >= 2 && j <= 17 && warp == (j & 3)) {
            const int jb = j & 1;
            mbar_wait(smb + 16 + jb * 8, ((j - 2) >> 1) & 1);   // empty[jb]
            stage_warp(smb + SM_S0 + jb * STG, j, t, gkh, gkl, gvh, gvl, lane);
            cp_mbar_arrive_noinc(smb + jb * 8);                 // full[jb]
        }
        mbar_wait(smb + b * 8, (i >> 1) & 1);   // full[b]
        const uint32_t kvb = smb + SM_S0 + b * STG;
        if (i == 0)      compute_chunk<2, true >(smb, kvb, o, m0, m1, l0, l1, lane, warp);
        else if (i == 1) compute_chunk<1, false>(smb, kvb, o, m0, m1, l0, l1, lane, warp);
        else             compute_chunk<2, false>(smb, kvb, o, m0, m1, l0, l1, lane, warp);
        if (lane == 0) mbar_arrive(smb + 16 + b * 8);           // empty[b]
    }

    // ---- epilogue (per-warp independent) ----
    const float inv0 = 1.f / l0, inv1 = 1.f / l1;
    #pragma unroll
    for (int dt = 0; dt < 8; dt++) {
        *reinterpret_cast<float2*>(Og + r0 * HD + dt * 8 + 2 * q4) =
            make_float2(o[dt].x * inv0, o[dt].y * inv0);
        *reinterpret_cast<float2*>(Og + (r0 + 8) * HD + dt * 8 + 2 * q4) =
            make_float2(o[dt].z * inv1, o[dt].w * inv1);
    }
}

extern "C" void kernel_launch(void* const* d_in, const int* in_sizes, int n_in,
                              void* d_out, int out_size)
{
    const float* Q = (const float*)d_in[0];
    const float* K = (const float*)d_in[1];
    const float* V = (const float*)d_in[2];
    float* O = (float*)d_out;

    const int nbh = in_sizes[0] / (SEQ * HD);      // 32
    const int n8  = nbh * SEQ * HD / 8;
    prepass_split<<<(n8 + 255) / 256, 256>>>(K, V, n8);

    cudaFuncSetAttribute(sparse_attn_bf16,
                         cudaFuncAttributeMaxDynamicSharedMemorySize, SM_TOTAL);
    dim3 grid(SEQ / 64, nbh);
    sparse_attn_bf16<<<grid, 128, SM_TOTAL>>>(Q, O);
}

// round 17
// speedup vs baseline: 1.2471x; 1.1972x over previous
#include <cuda_runtime.h>
#include <cuda_bf16.h>
#include <cuda_fp16.h>
#include <cstdint>

// DeepSpeed fixed sparse self-attention, B=2, H=16, S=2048, D=64, fp32.
// q-rows [64t,64t+64) attend window [64t,64t+48) + stripes [64m+48,64m+64), m=0..31.
// QK: mma.sync m16n8k16 bf16, EXACT 3-MMA split compensation (verified).
// PV (R17): fp16, 2 MMAs: O += Ph*Vh + Pl*Vh  (V single fp16; dropped term P*Vl
//           ~2^-12 relative). Softmax scale folded into Q at staging.
// R16 free-running mbarrier pipeline, rotating stager warp, 4 CTAs/SM x 128 thr.

#define SEQ 2048
#define HD  64
#define NBH 32
#define NEGBIG (-1e30f)
#define SC2 0.18033688011112042f   // 0.125 * log2(e), folded into Q

// smem layout (bytes)
#define SM_QH   128
#define SM_QL   (128 + 8192)
#define SM_S0   (128 + 16384)
#define STG     12288    // stage: KH +0, KL +4096, V16 +8192 (each 32 rows x 128B)
#define SM_TOTAL (128 + 16384 + 2 * 12288)   // 41088

__device__ __align__(16) __nv_bfloat16 g_Kh[(size_t)NBH*SEQ*HD];
__device__ __align__(16) __nv_bfloat16 g_Kl[(size_t)NBH*SEQ*HD];
__device__ __align__(16) __half        g_V16[(size_t)NBH*SEQ*HD];

__device__ __forceinline__ void mma_bf16(float4& d,
                                         uint32_t a0, uint32_t a1, uint32_t a2, uint32_t a3,
                                         uint32_t b0, uint32_t b1)
{
    asm volatile(
        "mma.sync.aligned.m16n8k16.row.col.f32.bf16.bf16.f32 "
        "{%0,%1,%2,%3}, {%4,%5,%6,%7}, {%8,%9}, {%0,%1,%2,%3};\n"
        : "+f"(d.x), "+f"(d.y), "+f"(d.z), "+f"(d.w)
        : "r"(a0), "r"(a1), "r"(a2), "r"(a3), "r"(b0), "r"(b1));
}

__device__ __forceinline__ void mma_f16(float4& d,
                                        uint32_t a0, uint32_t a1, uint32_t a2, uint32_t a3,
                                        uint32_t b0, uint32_t b1)
{
    asm volatile(
        "mma.sync.aligned.m16n8k16.row.col.f32.f16.f16.f32 "
        "{%0,%1,%2,%3}, {%4,%5,%6,%7}, {%8,%9}, {%0,%1,%2,%3};\n"
        : "+f"(d.x), "+f"(d.y), "+f"(d.z), "+f"(d.w)
        : "r"(a0), "r"(a1), "r"(a2), "r"(a3), "r"(b0), "r"(b1));
}

__device__ __forceinline__ void ldsm_x4(uint32_t& r0, uint32_t& r1, uint32_t& r2, uint32_t& r3,
                                        uint32_t addr)
{
    asm volatile("ldmatrix.sync.aligned.m8n8.x4.shared.b16 {%0,%1,%2,%3}, [%4];"
                 : "=r"(r0), "=r"(r1), "=r"(r2), "=r"(r3) : "r"(addr));
}

__device__ __forceinline__ void ldsm_x4_t(uint32_t& r0, uint32_t& r1, uint32_t& r2, uint32_t& r3,
                                          uint32_t addr)
{
    asm volatile("ldmatrix.sync.aligned.m8n8.x4.trans.shared.b16 {%0,%1,%2,%3}, [%4];"
                 : "=r"(r0), "=r"(r1), "=r"(r2), "=r"(r3) : "r"(addr));
}

// bf16 pair split (for Q/K)
__device__ __forceinline__ void split2(float a, float b, uint32_t& h, uint32_t& l)
{
    __nv_bfloat162 hv = __floats2bfloat162_rn(a, b);
    h = *reinterpret_cast<uint32_t*>(&hv);
    float ra = a - __bfloat162float(hv.x);
    float rb = b - __bfloat162float(hv.y);
    __nv_bfloat162 lv = __floats2bfloat162_rn(ra, rb);
    l = *reinterpret_cast<uint32_t*>(&lv);
}

// fp16 pair split (for P)
__device__ __forceinline__ void split2h(float a, float b, uint32_t& h, uint32_t& l)
{
    __half2 hv = __floats2half2_rn(a, b);
    h = *reinterpret_cast<uint32_t*>(&hv);
    float ra = a - __half2float(hv.x);
    float rb = b - __half2float(hv.y);
    __half2 lv = __floats2half2_rn(ra, rb);
    l = *reinterpret_cast<uint32_t*>(&lv);
}

__device__ __forceinline__ void cp16(uint32_t dst, const void* src)
{
    asm volatile("cp.async.ca.shared.global [%0], [%1], 16;\n" :: "r"(dst), "l"(src));
}

__device__ __forceinline__ void mbar_init(uint32_t addr, uint32_t count)
{
    asm volatile("mbarrier.init.shared.b64 [%0], %1;" :: "r"(addr), "r"(count) : "memory");
}
__device__ __forceinline__ void mbar_arrive(uint32_t addr)
{
    asm volatile("mbarrier.arrive.shared.b64 _, [%0];" :: "r"(addr) : "memory");
}
__device__ __forceinline__ void cp_mbar_arrive_noinc(uint32_t addr)
{
    asm volatile("cp.async.mbarrier.arrive.noinc.shared::cta.b64 [%0];"
                 :: "r"(addr) : "memory");
}
__device__ __forceinline__ void mbar_wait(uint32_t mbar, uint32_t parity)
{
    uint32_t done;
    asm volatile(
        "{\n\t.reg .pred p;\n\t"
        "mbarrier.try_wait.parity.acquire.cta.shared::cta.b64 p, [%1], %2;\n\t"
        "selp.b32 %0, 1, 0, p;\n\t}"
        : "=r"(done) : "r"(mbar), "r"(parity) : "memory");
    if (!done) {
        asm volatile(
            "{\n\t.reg .pred P1;\n\t"
            "WL_%=:\n\t"
            "mbarrier.try_wait.parity.acquire.cta.shared::cta.b64 P1, [%0], %1, 0x989680;\n\t"
            "@P1 bra.uni WD_%=;\n\t"
            "bra.uni WL_%=;\n\t"
            "WD_%=:\n\t}"
            :: "r"(mbar), "r"(parity) : "memory");
    }
}

// ================= prepass: K -> bf16 hi/lo, V -> fp16 single =================
__global__ void prepass_split(const float* __restrict__ K, const float* __restrict__ V, int n8)
{
    int i = blockIdx.x * blockDim.x + threadIdx.x;
    if (i >= n8) return;
    const float4* K4 = reinterpret_cast<const float4*>(K);
    const float4* V4 = reinterpret_cast<const float4*>(V);

    uint32_t h0,l0,h1,l1,h2,l2,h3,l3;
    float4 a = K4[2*i], b = K4[2*i+1];
    split2(a.x,a.y,h0,l0); split2(a.z,a.w,h1,l1);
    split2(b.x,b.y,h2,l2); split2(b.z,b.w,h3,l3);
    reinterpret_cast<uint4*>(g_Kh)[i] = make_uint4(h0,h1,h2,h3);
    reinterpret_cast<uint4*>(g_Kl)[i] = make_uint4(l0,l1,l2,l3);

    a = V4[2*i]; b = V4[2*i+1];
    __half2 v0 = __floats2half2_rn(a.x, a.y);
    __half2 v1 = __floats2half2_rn(a.z, a.w);
    __half2 v2 = __floats2half2_rn(b.x, b.y);
    __half2 v3 = __floats2half2_rn(b.z, b.w);
    reinterpret_cast<uint4*>(g_V16)[i] = make_uint4(
        *reinterpret_cast<uint32_t*>(&v0), *reinterpret_cast<uint32_t*>(&v1),
        *reinterpret_cast<uint32_t*>(&v2), *reinterpret_cast<uint32_t*>(&v3));
}

// ---- single-warp cp.async staging of chunk c into buffer kvb ----
// c0 = window keys 0..31, c1 = window 32..47 (16 keys),
// c in [2,18) = stripes 2(c-2), 2(c-2)+1 (keys 64m+48..64m+63 each).
__device__ __forceinline__ void stage_warp(uint32_t kvb, int c, int t,
                                           const uint4* gkh, const uint4* gkl,
                                           const uint4* gv, int lane)
{
    #pragma unroll
    for (int it = 0; it < 8; it++) {
        int idx = lane + it * 32;              // 0..255
        int row = idx >> 3, ch = idx & 7;      // row 0..31
        if (c == 1 && row >= 16) break;        // half chunk
        int gk;
        if (c == 0)      gk = t * 64 + row;
        else if (c == 1) gk = t * 64 + 32 + row;
        else {
            int stripe = 2 * (c - 2) + (row >> 4);   // 0..31
            gk = stripe * 64 + 48 + (row & 15);
        }
        size_t go = (size_t)gk * 8 + ch;
        uint32_t sw = (uint32_t)(row * 128 + ((ch ^ (row & 7)) << 4));
        cp16(kvb + sw,          gkh + go);
        cp16(kvb + 4096 + sw,   gkl + go);
        cp16(kvb + 8192 + sw,   gv + go);
    }
}

// ================= per-chunk compute =================
// NTP: x4 K-fragment pairs (1 => 16 keys, 2 => 32 keys).
template<int NTP, bool FIRST>
__device__ __forceinline__ void compute_chunk(
    uint32_t smb, uint32_t kvb, float4 (&o)[8],
    float& m0, float& m1, float& l0, float& l1, int lane, int warp)
{
    const int arow  = (warp << 4) + (((lane >> 3) & 1) << 3) + (lane & 7);
    const int krow0 = ((lane >> 4) << 3) + (lane & 7);
    const int kchp  = (lane >> 3) & 1;
    const int vrow0 = (((lane >> 3) & 1) << 3) + (lane & 7);
    const int vchp  = lane >> 4;

    float4 s[2 * NTP];
    #pragma unroll
    for (int i = 0; i < 2 * NTP; i++) s[i] = make_float4(0.f, 0.f, 0.f, 0.f);

    // ---- QK (exact 3-term bf16; Q pre-scaled by SC2) ----
    #pragma unroll
    for (int kb = 0; kb < 4; kb++) {
        const int qch = kb * 2 + (lane >> 4);
        const uint32_t qa = smb + SM_QH + arow * 128 + ((qch ^ (arow & 7)) << 4);
        uint32_t ah0, ah1, ah2, ah3, al0, al1, al2, al3;
        ldsm_x4(ah0, ah1, ah2, ah3, qa);
        ldsm_x4(al0, al1, al2, al3, qa + (SM_QL - SM_QH));
        #pragma unroll
        for (int ntp = 0; ntp < NTP; ntp++) {
            const int krow = ntp * 16 + krow0;
            const int kch  = kb * 2 + kchp;
            const uint32_t ka = kvb + krow * 128 + ((kch ^ (krow & 7)) << 4);
            uint32_t kl0, kl1, kl2, kl3, kh0, kh1, kh2, kh3;
            ldsm_x4(kl0, kl1, kl2, kl3, ka + 4096);   // K lo
            ldsm_x4(kh0, kh1, kh2, kh3, ka);          // K hi
            mma_bf16(s[2 * ntp],     ah0, ah1, ah2, ah3, kl0, kl1);   // Qh*Kl
            mma_bf16(s[2 * ntp],     al0, al1, al2, al3, kh0, kh1);   // Ql*Kh
            mma_bf16(s[2 * ntp],     ah0, ah1, ah2, ah3, kh0, kh1);   // Qh*Kh
            mma_bf16(s[2 * ntp + 1], ah0, ah1, ah2, ah3, kl2, kl3);
            mma_bf16(s[2 * ntp + 1], al0, al1, al2, al3, kh2, kh3);
            mma_bf16(s[2 * ntp + 1], ah0, ah1, ah2, ah3, kh2, kh3);
        }
    }

    // ---- streaming softmax (base-2; scale already in Q) ----
    float rm0 = NEGBIG, rm1 = NEGBIG;
    #pragma unroll
    for (int nt = 0; nt < 2 * NTP; nt++) {
        rm0 = fmaxf(rm0, fmaxf(s[nt].x, s[nt].y));
        rm1 = fmaxf(rm1, fmaxf(s[nt].z, s[nt].w));
    }
    rm0 = fmaxf(rm0, __shfl_xor_sync(0xffffffffu, rm0, 1));
    rm0 = fmaxf(rm0, __shfl_xor_sync(0xffffffffu, rm0, 2));
    rm1 = fmaxf(rm1, __shfl_xor_sync(0xffffffffu, rm1, 1));
    rm1 = fmaxf(rm1, __shfl_xor_sync(0xffffffffu, rm1, 2));

    float mn0, mn1;
    if (FIRST) { mn0 = rm0; mn1 = rm1; }
    else       { mn0 = fmaxf(m0, rm0); mn1 = fmaxf(m1, rm1); }

    float rs0 = 0.f, rs1 = 0.f;
    #pragma unroll
    for (int nt = 0; nt < 2 * NTP; nt++) {
        s[nt].x = exp2f(s[nt].x - mn0);
        s[nt].y = exp2f(s[nt].y - mn0);
        s[nt].z = exp2f(s[nt].z - mn1);
        s[nt].w = exp2f(s[nt].w - mn1);
        rs0 += s[nt].x + s[nt].y;
        rs1 += s[nt].z + s[nt].w;
    }
    rs0 += __shfl_xor_sync(0xffffffffu, rs0, 1);
    rs0 += __shfl_xor_sync(0xffffffffu, rs0, 2);
    rs1 += __shfl_xor_sync(0xffffffffu, rs1, 1);
    rs1 += __shfl_xor_sync(0xffffffffu, rs1, 2);

    if (FIRST) {
        l0 = rs0; l1 = rs1; m0 = mn0; m1 = mn1;
    } else {
        const float alp0 = exp2f(m0 - mn0), alp1 = exp2f(m1 - mn1);
        m0 = mn0; m1 = mn1;
        l0 = l0 * alp0 + rs0;
        l1 = l1 * alp1 + rs1;
        #pragma unroll
        for (int dt = 0; dt < 8; dt++) {
            o[dt].x *= alp0; o[dt].y *= alp0;
            o[dt].z *= alp1; o[dt].w *= alp1;
        }
    }

    // ---- PV (fp16, 2 MMAs: Ph*Vh + Pl*Vh; V single fp16) ----
    #pragma unroll
    for (int kb = 0; kb < NTP; kb++) {
        uint32_t ph0, pl0, ph1, pl1, ph2, pl2, ph3, pl3;
        split2h(s[2 * kb].x,     s[2 * kb].y,     ph0, pl0);
        split2h(s[2 * kb].z,     s[2 * kb].w,     ph1, pl1);
        split2h(s[2 * kb + 1].x, s[2 * kb + 1].y, ph2, pl2);
        split2h(s[2 * kb + 1].z, s[2 * kb + 1].w, ph3, pl3);
        const int vrow = kb * 16 + vrow0;
        #pragma unroll
        for (int dtp = 0; dtp < 4; dtp++) {
            const int vch = dtp * 2 + vchp;
            const uint32_t va = kvb + 8192 + vrow * 128 + ((vch ^ (vrow & 7)) << 4);
            uint32_t vh0, vh1, vh2, vh3;
            ldsm_x4_t(vh0, vh1, vh2, vh3, va);
            mma_f16(o[2 * dtp],     ph0, ph1, ph2, ph3, vh0, vh1);
            mma_f16(o[2 * dtp],     pl0, pl1, pl2, pl3, vh0, vh1);
            mma_f16(o[2 * dtp + 1], ph0, ph1, ph2, ph3, vh2, vh3);
            mma_f16(o[2 * dtp + 1], pl0, pl1, pl2, pl3, vh2, vh3);
        }
    }
}

// ================= main kernel =================
__global__ void __launch_bounds__(128, 4)
sparse_attn_bf16(const float* __restrict__ Q, float* __restrict__ Out)
{
    extern __shared__ __align__(16) char sm[];
    const uint32_t smb = (uint32_t)__cvta_generic_to_shared(sm);

    const int tid  = threadIdx.x;
    const int warp = tid >> 5;
    const int lane = tid & 31;
    const int g    = lane >> 2;
    const int q4   = lane & 3;
    const int t    = blockIdx.x;          // q tile 0..31
    const int bh   = blockIdx.y;

    const size_t base = (size_t)bh * SEQ * HD;
    const float* Qg = Q + base + (size_t)t * 64 * HD;
    float*       Og = Out + base + (size_t)t * 64 * HD;
    const uint4* gkh = reinterpret_cast<const uint4*>(g_Kh + base);
    const uint4* gkl = reinterpret_cast<const uint4*>(g_Kl + base);
    const uint4* gv  = reinterpret_cast<const uint4*>(g_V16 + base);

    // mbarriers: full[b] @ smb + b*8, empty[b] @ smb + 16 + b*8
    if (tid == 0) {
        mbar_init(smb + 0, 32);
        mbar_init(smb + 8, 32);
        mbar_init(smb + 16, 4);
        mbar_init(smb + 24, 4);
    }
    __syncthreads();

    // prologue staging: warp0 -> chunk0/buf0, warp1 -> chunk1/buf1
    if (warp == 0) {
        stage_warp(smb + SM_S0, 0, t, gkh, gkl, gv, lane);
        cp_mbar_arrive_noinc(smb + 0);
    } else if (warp == 1) {
        stage_warp(smb + SM_S0 + STG, 1, t, gkh, gkl, gv, lane);
        cp_mbar_arrive_noinc(smb + 8);
    }

    // ---- stage Q hi/lo, pre-scaled by SC2 ----
    #pragma unroll
    for (int it = 0; it < 4; it++) {
        int idx = tid + it * 128;             // 0..511
        int r = idx >> 3, ch = idx & 7;
        const float4* src = reinterpret_cast<const float4*>(Qg + r * HD + ch * 8);
        float4 a = src[0], b = src[1];
        a.x *= SC2; a.y *= SC2; a.z *= SC2; a.w *= SC2;
        b.x *= SC2; b.y *= SC2; b.z *= SC2; b.w *= SC2;
        uint32_t h0,l0,h1,l1,h2,l2,h3,l3;
        split2(a.x,a.y,h0,l0); split2(a.z,a.w,h1,l1);
        split2(b.x,b.y,h2,l2); split2(b.z,b.w,h3,l3);
        uint32_t sw = (uint32_t)(r * 128 + ((ch ^ (r & 7)) << 4));
        *reinterpret_cast<uint4*>(sm + SM_QH + sw) = make_uint4(h0,h1,h2,h3);
        *reinterpret_cast<uint4*>(sm + SM_QL + sw) = make_uint4(l0,l1,l2,l3);
    }
    __syncthreads();   // Q visible; loop below is free of CTA-wide barriers

    float4 o[8];
    #pragma unroll
    for (int i = 0; i < 8; i++) o[i] = make_float4(0.f, 0.f, 0.f, 0.f);
    float m0 = 0.f, m1 = 0.f, l0 = 0.f, l1 = 0.f;
    const int r0 = warp * 16 + g;

    // ---- 18 chunks, free-running warps, rotating stager ----
    #pragma unroll 1
    for (int i = 0; i < 18; i++) {
        const int b = i & 1;
        const int j = i + 1;
        if (j >= 2 && j <= 17 && warp == (j & 3)) {
            const int jb = j & 1;
            mbar_wait(smb + 16 + jb * 8, ((j - 2) >> 1) & 1);   // empty[jb]
            stage_warp(smb + SM_S0 + jb * STG, j, t, gkh, gkl, gv, lane);
            cp_mbar_arrive_noinc(smb + jb * 8);                 // full[jb]
        }
        mbar_wait(smb + b * 8, (i >> 1) & 1);                   // full[b]
        const uint32_t kvb = smb + SM_S0 + b * STG;
        if (i == 0)      compute_chunk<2, true >(smb, kvb, o, m0, m1, l0, l1, lane, warp);
        else if (i == 1) compute_chunk<1, false>(smb, kvb, o, m0, m1, l0, l1, lane, warp);
        else             compute_chunk<2, false>(smb, kvb, o, m0, m1, l0, l1, lane, warp);
        if (lane == 0) mbar_arrive(smb + 16 + b * 8);           // empty[b]
    }

    // ---- epilogue (per-warp independent) ----
    const float inv0 = 1.f / l0, inv1 = 1.f / l1;
    #pragma unroll
    for (int dt = 0; dt < 8; dt++) {
        *reinterpret_cast<float2*>(Og + r0 * HD + dt * 8 + 2 * q4) =
            make_float2(o[dt].x * inv0, o[dt].y * inv0);
        *reinterpret_cast<float2*>(Og + (r0 + 8) * HD + dt * 8 + 2 * q4) =
            make_float2(o[dt].z * inv1, o[dt].w * inv1);
    }
}

extern "C" void kernel_launch(void* const* d_in, const int* in_sizes, int n_in,
                              void* d_out, int out_size)
{
    const float* Q = (const float*)d_in[0];
    const float* K = (const float*)d_in[1];
    const float* V = (const float*)d_in[2];
    float* O = (float*)d_out;

    const int nbh = in_sizes[0] / (SEQ * HD);      // 32
    const int n8  = nbh * SEQ * HD / 8;
    prepass_split<<<(n8 + 255) / 256, 256>>>(K, V, n8);

    cudaFuncSetAttribute(sparse_attn_bf16,
                         cudaFuncAttributeMaxDynamicSharedMemorySize, SM_TOTAL);
    dim3 grid(SEQ / 64, nbh);
    sparse_attn_bf16<<<grid, 128, SM_TOTAL>>>(Q, O);
}